// round 1
// baseline (speedup 1.0000x reference)
#include <cuda_runtime.h>
#include <math.h>
#include <stdint.h>

// MedicalMoE: B=16384 tokens, D=1024, H=4096, E=8 experts, top-2, gating hidden 256.
// Strategy: gate (fp32) -> counting-sort dispatch -> per-expert grouped SGEMM
// (gather A rows in GEMM1, scatter weighted output via atomicAdd in GEMM2).

#define BT 16384
#define DM 1024
#define HE 4096
#define NE 8
#define TK 2
#define GHD 256

#define NROWS (BT * TK)   // 32768 total expert-row assignments

// ------------------------- scratch (__device__ globals) -------------------------
__device__ float g_hidden[(size_t)BT * GHD];          // 16 MB  gating hidden
__device__ int   g_counts[NE];
__device__ int   g_starts[NE];
__device__ int   g_fill[NE];
__device__ int   g_eid[NROWS];                        // per token: 2 expert ids
__device__ float g_ew[NROWS];                         // per token: 2 weights
__device__ int   g_rowmap[NROWS];                     // pos -> token
__device__ float g_roww[NROWS];                       // pos -> combine weight
__device__ float g_h[(size_t)NROWS * HE];             // 512 MB  tanh activations

// ------------------------- small setup kernels -------------------------
__global__ void k_init()
{
    if (threadIdx.x < NE) g_counts[threadIdx.x] = 0;
}

__global__ void k_scan()
{
    int s = 0;
    for (int e = 0; e < NE; e++) {
        g_starts[e] = s;
        s += g_counts[e];
        g_fill[e] = 0;
    }
}

__global__ void k_scatter()
{
    int t = blockIdx.x * blockDim.x + threadIdx.x;
    if (t >= BT) return;
#pragma unroll
    for (int k = 0; k < TK; k++) {
        int e = g_eid[t * TK + k];
        int pos = g_starts[e] + atomicAdd(&g_fill[e], 1);
        g_rowmap[pos] = t;
        g_roww[pos]   = g_ew[t * TK + k];
    }
}

// ------------------------- gating GEMM1: hidden = relu(x @ gw1 + gb1) -------------------------
// C[BT, 256] = relu(X[BT,1024] @ W[1024,256] + b). Tile 128x128x8, 256 thr, 8x8/thread.
__global__ __launch_bounds__(256) void k_gate_gemm(
    const float* __restrict__ X, const float* __restrict__ W, const float* __restrict__ bias)
{
    const int K = DM, N = GHD;
    __shared__ float As[8][128];
    __shared__ float Bs[8][128];

    int tid  = threadIdx.x;
    int row0 = blockIdx.y * 128;
    int col0 = blockIdx.x * 128;

    int arow = tid >> 1, acol = (tid & 1) * 4;     // A tile load: 128 rows x 8 k
    int brow = tid >> 5, bcol = (tid & 31) * 4;    // B tile load: 8 k x 128 cols
    int tx = tid & 15,  ty = tid >> 4;

    float acc[8][8];
#pragma unroll
    for (int i = 0; i < 8; i++)
#pragma unroll
        for (int j = 0; j < 8; j++) acc[i][j] = 0.f;

    const float* Aptr = X + (size_t)(row0 + arow) * K + acol;
    const float* Bptr = W + (size_t)brow * N + col0 + bcol;

    for (int k0 = 0; k0 < K; k0 += 8) {
        float4 av = *(const float4*)(Aptr + k0);
        As[acol + 0][arow] = av.x; As[acol + 1][arow] = av.y;
        As[acol + 2][arow] = av.z; As[acol + 3][arow] = av.w;
        float4 bv = *(const float4*)(Bptr + (size_t)k0 * N);
        *(float4*)&Bs[brow][bcol] = bv;
        __syncthreads();
#pragma unroll
        for (int kk = 0; kk < 8; kk++) {
            float a[8], b[8];
            float4 t0 = *(const float4*)&As[kk][ty * 4];
            float4 t1 = *(const float4*)&As[kk][64 + ty * 4];
            a[0]=t0.x; a[1]=t0.y; a[2]=t0.z; a[3]=t0.w;
            a[4]=t1.x; a[5]=t1.y; a[6]=t1.z; a[7]=t1.w;
            float4 u0 = *(const float4*)&Bs[kk][tx * 4];
            float4 u1 = *(const float4*)&Bs[kk][64 + tx * 4];
            b[0]=u0.x; b[1]=u0.y; b[2]=u0.z; b[3]=u0.w;
            b[4]=u1.x; b[5]=u1.y; b[6]=u1.z; b[7]=u1.w;
#pragma unroll
            for (int i = 0; i < 8; i++)
#pragma unroll
                for (int j = 0; j < 8; j++) acc[i][j] += a[i] * b[j];
        }
        __syncthreads();
    }

#pragma unroll
    for (int i = 0; i < 8; i++) {
        int r = row0 + ((i < 4) ? (ty * 4 + i) : (64 + ty * 4 + (i - 4)));
#pragma unroll
        for (int j = 0; j < 8; j++) {
            int c = col0 + ((j < 4) ? (tx * 4 + j) : (64 + tx * 4 + (j - 4)));
            float v = acc[i][j] + bias[c];
            g_hidden[(size_t)r * N + c] = v > 0.f ? v : 0.f;
        }
    }
}

// ------------------------- gate head: logits -> softmax -> top2 -------------------------
// one warp per token; 8 tokens per block
__global__ __launch_bounds__(256) void k_gate2(
    const float* __restrict__ gw2, const float* __restrict__ gb2, float* tail)
{
    __shared__ float sW[GHD * NE];
    __shared__ float sb[NE];
    int tid = threadIdx.x;
    for (int i = tid; i < GHD * NE; i += 256) sW[i] = gw2[i];
    if (tid < NE) sb[tid] = gb2[tid];
    __syncthreads();

    int warp = tid >> 5, lane = tid & 31;
    int token = blockIdx.x * 8 + warp;
    const float* hrow = g_hidden + (size_t)token * GHD;

    float l[NE];
#pragma unroll
    for (int e = 0; e < NE; e++) l[e] = 0.f;
#pragma unroll
    for (int i = 0; i < GHD / 32; i++) {
        int r = lane + i * 32;
        float hv = hrow[r];
#pragma unroll
        for (int e = 0; e < NE; e++) l[e] += hv * sW[r * NE + e];
    }
#pragma unroll
    for (int off = 16; off > 0; off >>= 1)
#pragma unroll
        for (int e = 0; e < NE; e++) l[e] += __shfl_down_sync(0xffffffffu, l[e], off);

    if (lane == 0) {
        float p[NE];
        float m = -1e30f;
#pragma unroll
        for (int e = 0; e < NE; e++) { l[e] += sb[e]; m = fmaxf(m, l[e]); }
        float s = 0.f;
#pragma unroll
        for (int e = 0; e < NE; e++) { p[e] = expf(l[e] - m); s += p[e]; }
        float inv = 1.f / s;
#pragma unroll
        for (int e = 0; e < NE; e++) p[e] *= inv;

        // top-2, ties -> lower index (matches lax.top_k)
        int b0 = 0; float v0 = p[0];
#pragma unroll
        for (int e = 1; e < NE; e++) if (p[e] > v0) { v0 = p[e]; b0 = e; }
        int b1 = -1; float v1 = -1e30f;
#pragma unroll
        for (int e = 0; e < NE; e++) if (e != b0 && p[e] > v1) { v1 = p[e]; b1 = e; }

        float d = 1.f / (v0 + v1);
        g_eid[token * TK + 0] = b0;  g_ew[token * TK + 0] = v0 * d;
        g_eid[token * TK + 1] = b1;  g_ew[token * TK + 1] = v1 * d;
        atomicAdd(&g_counts[b0], 1);
        atomicAdd(&g_counts[b1], 1);
        if (tail) {
            tail[token * TK + 0] = (float)b0;
            tail[token * TK + 1] = (float)b1;
        }
    }
}

// ------------------------- expert GEMM1: h = tanh(gather(x) @ ew1[e] + eb1[e]) -------------------------
__global__ __launch_bounds__(256) void k_exp1(
    const float* __restrict__ X, const float* __restrict__ EW1, const float* __restrict__ EB1)
{
    const int K = DM, N = HE;
    int e = blockIdx.z;
    int rows = g_counts[e];
    int base = g_starts[e];
    int row0 = blockIdx.y * 128;
    if (row0 >= rows) return;
    int col0 = blockIdx.x * 128;

    __shared__ float As[8][128];
    __shared__ float Bs[8][128];

    int tid  = threadIdx.x;
    int arow = tid >> 1, acol = (tid & 1) * 4;
    int brow = tid >> 5, bcol = (tid & 31) * 4;
    int tx = tid & 15,  ty = tid >> 4;

    int grow = row0 + arow;
    int tok  = g_rowmap[base + (grow < rows ? grow : rows - 1)];  // gather (clamped)
    const float* Aptr = X + (size_t)tok * K + acol;
    const float* W    = EW1 + (size_t)e * K * N;
    const float* Bptr = W + (size_t)brow * N + col0 + bcol;

    float acc[8][8];
#pragma unroll
    for (int i = 0; i < 8; i++)
#pragma unroll
        for (int j = 0; j < 8; j++) acc[i][j] = 0.f;

    for (int k0 = 0; k0 < K; k0 += 8) {
        float4 av = *(const float4*)(Aptr + k0);
        As[acol + 0][arow] = av.x; As[acol + 1][arow] = av.y;
        As[acol + 2][arow] = av.z; As[acol + 3][arow] = av.w;
        float4 bv = *(const float4*)(Bptr + (size_t)k0 * N);
        *(float4*)&Bs[brow][bcol] = bv;
        __syncthreads();
#pragma unroll
        for (int kk = 0; kk < 8; kk++) {
            float a[8], b[8];
            float4 t0 = *(const float4*)&As[kk][ty * 4];
            float4 t1 = *(const float4*)&As[kk][64 + ty * 4];
            a[0]=t0.x; a[1]=t0.y; a[2]=t0.z; a[3]=t0.w;
            a[4]=t1.x; a[5]=t1.y; a[6]=t1.z; a[7]=t1.w;
            float4 u0 = *(const float4*)&Bs[kk][tx * 4];
            float4 u1 = *(const float4*)&Bs[kk][64 + tx * 4];
            b[0]=u0.x; b[1]=u0.y; b[2]=u0.z; b[3]=u0.w;
            b[4]=u1.x; b[5]=u1.y; b[6]=u1.z; b[7]=u1.w;
#pragma unroll
            for (int i = 0; i < 8; i++)
#pragma unroll
                for (int j = 0; j < 8; j++) acc[i][j] += a[i] * b[j];
        }
        __syncthreads();
    }

#pragma unroll
    for (int i = 0; i < 8; i++) {
        int rl = (i < 4) ? (ty * 4 + i) : (64 + ty * 4 + (i - 4));
        int r  = row0 + rl;
        if (r < rows) {
            size_t prow = (size_t)(base + r) * N;
#pragma unroll
            for (int j = 0; j < 8; j++) {
                int c = col0 + ((j < 4) ? (tx * 4 + j) : (64 + tx * 4 + (j - 4)));
                g_h[prow + c] = tanhf(acc[i][j] + EB1[e * N + c]);
            }
        }
    }
}

// ------------------------- expert GEMM2: out[token] += w * (h @ ew2[e] + eb2[e]) -------------------------
__global__ __launch_bounds__(256) void k_exp2(
    const float* __restrict__ EW2, const float* __restrict__ EB2, float* __restrict__ out)
{
    const int K = HE, N = DM;
    int e = blockIdx.z;
    int rows = g_counts[e];
    int base = g_starts[e];
    int row0 = blockIdx.y * 128;
    if (row0 >= rows) return;
    int col0 = blockIdx.x * 128;

    __shared__ float As[8][128];
    __shared__ float Bs[8][128];

    int tid  = threadIdx.x;
    int arow = tid >> 1, acol = (tid & 1) * 4;
    int brow = tid >> 5, bcol = (tid & 31) * 4;
    int tx = tid & 15,  ty = tid >> 4;

    int grow = row0 + arow;
    int gpos = base + (grow < rows ? grow : rows - 1);
    const float* Aptr = g_h + (size_t)gpos * K + acol;   // h rows are contiguous per expert
    const float* W    = EW2 + (size_t)e * K * N;
    const float* Bptr = W + (size_t)brow * N + col0 + bcol;

    float acc[8][8];
#pragma unroll
    for (int i = 0; i < 8; i++)
#pragma unroll
        for (int j = 0; j < 8; j++) acc[i][j] = 0.f;

    for (int k0 = 0; k0 < K; k0 += 8) {
        float4 av = *(const float4*)(Aptr + k0);
        As[acol + 0][arow] = av.x; As[acol + 1][arow] = av.y;
        As[acol + 2][arow] = av.z; As[acol + 3][arow] = av.w;
        float4 bv = *(const float4*)(Bptr + (size_t)k0 * N);
        *(float4*)&Bs[brow][bcol] = bv;
        __syncthreads();
#pragma unroll
        for (int kk = 0; kk < 8; kk++) {
            float a[8], b[8];
            float4 t0 = *(const float4*)&As[kk][ty * 4];
            float4 t1 = *(const float4*)&As[kk][64 + ty * 4];
            a[0]=t0.x; a[1]=t0.y; a[2]=t0.z; a[3]=t0.w;
            a[4]=t1.x; a[5]=t1.y; a[6]=t1.z; a[7]=t1.w;
            float4 u0 = *(const float4*)&Bs[kk][tx * 4];
            float4 u1 = *(const float4*)&Bs[kk][64 + tx * 4];
            b[0]=u0.x; b[1]=u0.y; b[2]=u0.z; b[3]=u0.w;
            b[4]=u1.x; b[5]=u1.y; b[6]=u1.z; b[7]=u1.w;
#pragma unroll
            for (int i = 0; i < 8; i++)
#pragma unroll
                for (int j = 0; j < 8; j++) acc[i][j] += a[i] * b[j];
        }
        __syncthreads();
    }

#pragma unroll
    for (int i = 0; i < 8; i++) {
        int rl = (i < 4) ? (ty * 4 + i) : (64 + ty * 4 + (i - 4));
        int r  = row0 + rl;
        if (r < rows) {
            int pos = base + r;
            int tok = g_rowmap[pos];
            float w = g_roww[pos];
            size_t orow = (size_t)tok * N;
#pragma unroll
            for (int j = 0; j < 8; j++) {
                int c = col0 + ((j < 4) ? (tx * 4 + j) : (64 + tx * 4 + (j - 4)));
                atomicAdd(&out[orow + c], w * (acc[i][j] + EB2[e * N + c]));
            }
        }
    }
}

// ------------------------- launch -------------------------
extern "C" void kernel_launch(void* const* d_in, const int* in_sizes, int n_in,
                              void* d_out, int out_size)
{
    const float* x   = (const float*)d_in[0];
    const float* gw1 = (const float*)d_in[1];
    const float* gb1 = (const float*)d_in[2];
    const float* gw2 = (const float*)d_in[3];
    const float* gb2 = (const float*)d_in[4];
    const float* ew1 = (const float*)d_in[5];
    const float* eb1 = (const float*)d_in[6];
    const float* ew2 = (const float*)d_in[7];
    const float* eb2 = (const float*)d_in[8];
    float* out = (float*)d_out;

    cudaMemsetAsync(d_out, 0, (size_t)out_size * sizeof(float));
    k_init<<<1, 32>>>();

    dim3 gg(GHD / 128, BT / 128);
    k_gate_gemm<<<gg, 256>>>(x, gw1, gb1);

    // if the harness output includes the topk_idx tuple element, write it as float32
    long long extra = (long long)out_size - (long long)BT * DM;
    float* tail = (extra >= (long long)BT * TK) ? (out + (size_t)BT * DM) : nullptr;
    k_gate2<<<BT / 8, 256>>>(gw2, gb2, tail);

    k_scan<<<1, 1>>>();
    k_scatter<<<BT / 256, 256>>>();

    dim3 ge1(HE / 128, BT / 128, NE);
    k_exp1<<<ge1, 256>>>(x, ew1, eb1);

    dim3 ge2(DM / 128, BT / 128, NE);
    k_exp2<<<ge2, 256>>>(ew2, eb2, out);
}

// round 7
// speedup vs baseline: 1.9618x; 1.9618x over previous
#include <cuda_runtime.h>
#include <cuda_bf16.h>
#include <math.h>
#include <stdint.h>

// MedicalMoE on GB300 (plain sm_103 target).
// gate fp32 -> dispatch -> bf16x3 compensated mma.sync expert GEMMs.
// Round-7 fix: routing is SKEWED (shared gw2 + relu positive mean => common
// logit component), so a single expert can receive up to BT rows. Grid must
// cover BT rows per expert, not BT*TK/NE.
#define BT 16384
#define DM 1024
#define HE 4096
#define NE 8
#define TK 2
#define GHD 256
#define NROWS (BT * TK)
#define MAXROWS_PER_E BT      // a token selects an expert at most once
#define KCH 32
#define SA 40   // smem row stride in elements (32 + 8 pad)

// ------------------------- device scratch -------------------------
__device__ float g_hidden[(size_t)BT * GHD];
__device__ int   g_counts[NE];
__device__ int   g_starts[NE];
__device__ int   g_fill[NE];
__device__ int   g_eid[NROWS];
__device__ float g_ew[NROWS];
__device__ int   g_rowmap[NROWS];
__device__ float g_roww[NROWS];
__device__ __nv_bfloat16 g_xh[(size_t)BT * DM],  g_xl[(size_t)BT * DM];
__device__ __nv_bfloat16 g_w1h[(size_t)NE * DM * HE], g_w1l[(size_t)NE * DM * HE]; // [E][K][N]
__device__ __nv_bfloat16 g_w2h[(size_t)NE * HE * DM], g_w2l[(size_t)NE * HE * DM]; // [E][K][N]
__device__ __nv_bfloat16 g_hh[(size_t)NROWS * HE], g_hl[(size_t)NROWS * HE];

#define MMA16816(d, a, b) \
    asm volatile("mma.sync.aligned.m16n8k16.row.col.f32.bf16.bf16.f32 " \
        "{%0,%1,%2,%3}, {%4,%5,%6,%7}, {%8,%9}, {%0,%1,%2,%3};" \
        : "+f"((d)[0]),"+f"((d)[1]),"+f"((d)[2]),"+f"((d)[3]) \
        : "r"((a)[0]),"r"((a)[1]),"r"((a)[2]),"r"((a)[3]),"r"((b)[0]),"r"((b)[1]))

// ------------------------- setup kernels -------------------------
__global__ void k_init() { if (threadIdx.x < NE) g_counts[threadIdx.x] = 0; }

__global__ void k_scan() {
    int s = 0;
    for (int e = 0; e < NE; e++) { g_starts[e] = s; s += g_counts[e]; g_fill[e] = 0; }
}

__global__ void k_scatter() {
    int t = blockIdx.x * blockDim.x + threadIdx.x;
    if (t >= BT) return;
#pragma unroll
    for (int k = 0; k < TK; k++) {
        int e = g_eid[t * TK + k];
        int pos = g_starts[e] + atomicAdd(&g_fill[e], 1);
        g_rowmap[pos] = t;
        g_roww[pos] = g_ew[t * TK + k];
    }
}

__global__ __launch_bounds__(256) void k_xsplit(const float* __restrict__ x) {
    size_t i = (size_t)blockIdx.x * 256 + threadIdx.x;
    float v = x[i];
    __nv_bfloat16 h = __float2bfloat16(v);
    g_xh[i] = h;
    g_xl[i] = __float2bfloat16(v - __bfloat162float(h));
}

// hi/lo split of expert weights; destinations selected in device code only.
template <int W2>
__global__ __launch_bounds__(256) void k_wsplit(const float* __restrict__ W)
{
    size_t i = (size_t)blockIdx.x * 256 + threadIdx.x;
    float v = W[i];
    __nv_bfloat16 h = __float2bfloat16(v);
    __nv_bfloat16 l = __float2bfloat16(v - __bfloat162float(h));
    if (W2) { g_w2h[i] = h; g_w2l[i] = l; }
    else    { g_w1h[i] = h; g_w1l[i] = l; }
}

// ------------------------- gating (fp32, proven round 1) -------------------------
__global__ __launch_bounds__(256) void k_gate_gemm(
    const float* __restrict__ X, const float* __restrict__ W, const float* __restrict__ bias)
{
    const int K = DM, N = GHD;
    __shared__ float As[8][128];
    __shared__ float Bs[8][128];
    int tid = threadIdx.x;
    int row0 = blockIdx.y * 128, col0 = blockIdx.x * 128;
    int arow = tid >> 1, acol = (tid & 1) * 4;
    int brow = tid >> 5, bcol = (tid & 31) * 4;
    int tx = tid & 15, ty = tid >> 4;
    float acc[8][8];
#pragma unroll
    for (int i = 0; i < 8; i++)
#pragma unroll
        for (int j = 0; j < 8; j++) acc[i][j] = 0.f;
    const float* Aptr = X + (size_t)(row0 + arow) * K + acol;
    const float* Bptr = W + (size_t)brow * N + col0 + bcol;
    for (int k0 = 0; k0 < K; k0 += 8) {
        float4 av = *(const float4*)(Aptr + k0);
        As[acol + 0][arow] = av.x; As[acol + 1][arow] = av.y;
        As[acol + 2][arow] = av.z; As[acol + 3][arow] = av.w;
        *(float4*)&Bs[brow][bcol] = *(const float4*)(Bptr + (size_t)k0 * N);
        __syncthreads();
#pragma unroll
        for (int kk = 0; kk < 8; kk++) {
            float a[8], b[8];
            float4 t0 = *(const float4*)&As[kk][ty * 4];
            float4 t1 = *(const float4*)&As[kk][64 + ty * 4];
            a[0]=t0.x;a[1]=t0.y;a[2]=t0.z;a[3]=t0.w;a[4]=t1.x;a[5]=t1.y;a[6]=t1.z;a[7]=t1.w;
            float4 u0 = *(const float4*)&Bs[kk][tx * 4];
            float4 u1 = *(const float4*)&Bs[kk][64 + tx * 4];
            b[0]=u0.x;b[1]=u0.y;b[2]=u0.z;b[3]=u0.w;b[4]=u1.x;b[5]=u1.y;b[6]=u1.z;b[7]=u1.w;
#pragma unroll
            for (int i = 0; i < 8; i++)
#pragma unroll
                for (int j = 0; j < 8; j++) acc[i][j] += a[i] * b[j];
        }
        __syncthreads();
    }
#pragma unroll
    for (int i = 0; i < 8; i++) {
        int r = row0 + ((i < 4) ? (ty * 4 + i) : (64 + ty * 4 + (i - 4)));
#pragma unroll
        for (int j = 0; j < 8; j++) {
            int c = col0 + ((j < 4) ? (tx * 4 + j) : (64 + tx * 4 + (j - 4)));
            float v = acc[i][j] + bias[c];
            g_hidden[(size_t)r * GHD + c] = v > 0.f ? v : 0.f;
        }
    }
}

__global__ __launch_bounds__(256) void k_gate2(
    const float* __restrict__ gw2, const float* __restrict__ gb2, float* tail)
{
    __shared__ float sW[GHD * NE];
    __shared__ float sb[NE];
    int tid = threadIdx.x;
    for (int i = tid; i < GHD * NE; i += 256) sW[i] = gw2[i];
    if (tid < NE) sb[tid] = gb2[tid];
    __syncthreads();
    int warp = tid >> 5, lane = tid & 31;
    int token = blockIdx.x * 8 + warp;
    const float* hrow = g_hidden + (size_t)token * GHD;
    float l[NE];
#pragma unroll
    for (int e = 0; e < NE; e++) l[e] = 0.f;
#pragma unroll
    for (int i = 0; i < GHD / 32; i++) {
        int r = lane + i * 32;
        float hv = hrow[r];
#pragma unroll
        for (int e = 0; e < NE; e++) l[e] += hv * sW[r * NE + e];
    }
#pragma unroll
    for (int off = 16; off > 0; off >>= 1)
#pragma unroll
        for (int e = 0; e < NE; e++) l[e] += __shfl_down_sync(0xffffffffu, l[e], off);
    if (lane == 0) {
        float p[NE]; float m = -1e30f;
#pragma unroll
        for (int e = 0; e < NE; e++) { l[e] += sb[e]; m = fmaxf(m, l[e]); }
        float s = 0.f;
#pragma unroll
        for (int e = 0; e < NE; e++) { p[e] = expf(l[e] - m); s += p[e]; }
        float inv = 1.f / s;
#pragma unroll
        for (int e = 0; e < NE; e++) p[e] *= inv;
        int b0 = 0; float v0 = p[0];
#pragma unroll
        for (int e = 1; e < NE; e++) if (p[e] > v0) { v0 = p[e]; b0 = e; }
        int b1 = -1; float v1 = -1e30f;
#pragma unroll
        for (int e = 0; e < NE; e++) if (e != b0 && p[e] > v1) { v1 = p[e]; b1 = e; }
        float d = 1.f / (v0 + v1);
        g_eid[token * TK + 0] = b0; g_ew[token * TK + 0] = v0 * d;
        g_eid[token * TK + 1] = b1; g_ew[token * TK + 1] = v1 * d;
        atomicAdd(&g_counts[b0], 1);
        atomicAdd(&g_counts[b1], 1);
        if (tail) { tail[token * TK + 0] = (float)b0; tail[token * TK + 1] = (float)b1; }
    }
}

// ------------------------- bf16x3 mma.sync grouped GEMM (plain C++ data path) -----
// CTA tile 128(M) x 128(N), K-chunk 32. Static smem: A[m][k] hi/lo, B^T[n][k] hi/lo.
// MODE 0: GEMM1 (A = gathered x hi/lo, epilogue tanh -> g_hh/g_hl)
// MODE 1: GEMM2 (A = contiguous h rows, epilogue weighted atomicAdd -> out)
template <int KDIM, int NDIM, int MODE>
__global__ __launch_bounds__(256) void k_moe_mma(const float* __restrict__ bias,
                                                 float* __restrict__ out)
{
    __shared__ __nv_bfloat16 sAh[128 * SA], sAl[128 * SA];
    __shared__ __nv_bfloat16 sBh[128 * SA], sBl[128 * SA];

    int e = blockIdx.z;
    int rows = g_counts[e];
    int base = g_starts[e];
    int row0 = blockIdx.y * 128;
    if (row0 >= rows) return;
    int col0 = blockIdx.x * 128;

    int tid = threadIdx.x, wid = tid >> 5, lane = tid & 31;
    int gid = lane >> 2, tig = lane & 3;
    int warp_m = wid & 3, warp_n = wid >> 2;

    // ---- global source mapping ----
    int arow = tid >> 1, aseg = tid & 1;           // A: 2 threads/row, 2 uint4 each
    int bk = tid >> 3, bseg = tid & 7;             // B: 8 threads/k-row, 2 uint4 each
    int arc = (row0 + arow < rows) ? (row0 + arow) : (rows - 1);
    const __nv_bfloat16 *APH, *APL;
    size_t aoff;
    if (MODE == 0) {
        APH = g_xh; APL = g_xl;
        aoff = (size_t)g_rowmap[base + arc] * KDIM;
    } else {
        APH = g_hh; APL = g_hl;
        aoff = (size_t)(base + arc) * KDIM;
    }
    const __nv_bfloat16* BPH = (MODE == 0 ? g_w1h : g_w2h) + (size_t)e * KDIM * NDIM;
    const __nv_bfloat16* BPL = (MODE == 0 ? g_w1l : g_w2l) + (size_t)e * KDIM * NDIM;

    float acc[2][8][4];
#pragma unroll
    for (int mf = 0; mf < 2; mf++)
#pragma unroll
        for (int nf = 0; nf < 8; nf++)
#pragma unroll
            for (int q = 0; q < 4; q++) acc[mf][nf][q] = 0.f;

    uint4 pa[4], pb[4];   // prefetch registers (Ah x2, Al x2 / Bh x2, Bl x2)
    auto fetch = [&](int kc) {
        const uint4* ah = (const uint4*)(APH + aoff + kc * KCH);
        const uint4* al = (const uint4*)(APL + aoff + kc * KCH);
        pa[0] = ah[aseg * 2];  pa[1] = ah[aseg * 2 + 1];
        pa[2] = al[aseg * 2];  pa[3] = al[aseg * 2 + 1];
        const uint4* bh = (const uint4*)(BPH + (size_t)(kc * KCH + bk) * NDIM + col0);
        const uint4* bl = (const uint4*)(BPL + (size_t)(kc * KCH + bk) * NDIM + col0);
        pb[0] = bh[bseg * 2];  pb[1] = bh[bseg * 2 + 1];
        pb[2] = bl[bseg * 2];  pb[3] = bl[bseg * 2 + 1];
    };
    auto store_smem = [&]() {
        *(uint4*)&sAh[arow * SA + aseg * 16]     = pa[0];
        *(uint4*)&sAh[arow * SA + aseg * 16 + 8] = pa[1];
        *(uint4*)&sAl[arow * SA + aseg * 16]     = pa[2];
        *(uint4*)&sAl[arow * SA + aseg * 16 + 8] = pa[3];
        const __nv_bfloat16* eh = (const __nv_bfloat16*)&pb[0];   // 16 hi n-values
        const __nv_bfloat16* el = (const __nv_bfloat16*)&pb[2];   // 16 lo n-values
#pragma unroll
        for (int j = 0; j < 16; j++) {
            sBh[(bseg * 16 + j) * SA + bk] = eh[j];   // transpose: [n][k]
            sBl[(bseg * 16 + j) * SA + bk] = el[j];
        }
    };

    const int NK = KDIM / KCH;
    fetch(0);
    store_smem();
    __syncthreads();

    for (int kc = 0; kc < NK; kc++) {
        if (kc + 1 < NK) fetch(kc + 1);   // global prefetch overlaps compute below
#pragma unroll
        for (int ks = 0; ks < 2; ks++) {
            int kcol = ks * 16 + tig * 2;
            uint32_t a_h[2][4], a_l[2][4];
#pragma unroll
            for (int mf = 0; mf < 2; mf++) {
                int mrow = warp_m * 32 + mf * 16 + gid;
                a_h[mf][0] = *(const uint32_t*)&sAh[mrow * SA + kcol];
                a_h[mf][1] = *(const uint32_t*)&sAh[(mrow + 8) * SA + kcol];
                a_h[mf][2] = *(const uint32_t*)&sAh[mrow * SA + kcol + 8];
                a_h[mf][3] = *(const uint32_t*)&sAh[(mrow + 8) * SA + kcol + 8];
                a_l[mf][0] = *(const uint32_t*)&sAl[mrow * SA + kcol];
                a_l[mf][1] = *(const uint32_t*)&sAl[(mrow + 8) * SA + kcol];
                a_l[mf][2] = *(const uint32_t*)&sAl[mrow * SA + kcol + 8];
                a_l[mf][3] = *(const uint32_t*)&sAl[(mrow + 8) * SA + kcol + 8];
            }
#pragma unroll
            for (int nf = 0; nf < 8; nf++) {
                int n = warp_n * 64 + nf * 8 + gid;
                uint32_t b_h[2], b_l[2];
                b_h[0] = *(const uint32_t*)&sBh[n * SA + kcol];
                b_h[1] = *(const uint32_t*)&sBh[n * SA + kcol + 8];
                b_l[0] = *(const uint32_t*)&sBl[n * SA + kcol];
                b_l[1] = *(const uint32_t*)&sBl[n * SA + kcol + 8];
#pragma unroll
                for (int mf = 0; mf < 2; mf++) {
                    MMA16816(acc[mf][nf], a_h[mf], b_h);
                    MMA16816(acc[mf][nf], a_h[mf], b_l);
                    MMA16816(acc[mf][nf], a_l[mf], b_h);
                }
            }
        }
        __syncthreads();
        if (kc + 1 < NK) {
            store_smem();
            __syncthreads();
        }
    }

    // ---- epilogue (register accumulators) ----
    int rb = row0 + warp_m * 32 + gid;
    int cb = col0 + warp_n * 64 + tig * 2;
    const float* bp = bias + (size_t)e * NDIM;
#pragma unroll
    for (int mf = 0; mf < 2; mf++) {
#pragma unroll
        for (int half2 = 0; half2 < 2; half2++) {
            int r = rb + mf * 16 + half2 * 8;
            if (r >= rows) continue;
            size_t orow; float wgt = 1.f;
            if (MODE == 0) {
                orow = (size_t)(base + r) * NDIM;
            } else {
                int pos = base + r;
                orow = (size_t)g_rowmap[pos] * NDIM;
                wgt = g_roww[pos];
            }
#pragma unroll
            for (int nf = 0; nf < 8; nf++) {
                int c = cb + nf * 8;
                float v0 = acc[mf][nf][half2 * 2 + 0] + bp[c];
                float v1 = acc[mf][nf][half2 * 2 + 1] + bp[c + 1];
                if (MODE == 0) {
                    float t0 = tanhf(v0), t1 = tanhf(v1);
                    __nv_bfloat16 h0 = __float2bfloat16(t0), h1 = __float2bfloat16(t1);
                    __nv_bfloat16 l0 = __float2bfloat16(t0 - __bfloat162float(h0));
                    __nv_bfloat16 l1 = __float2bfloat16(t1 - __bfloat162float(h1));
                    uint32_t ph = ((uint32_t)__bfloat16_as_ushort(h1) << 16) | __bfloat16_as_ushort(h0);
                    uint32_t pl = ((uint32_t)__bfloat16_as_ushort(l1) << 16) | __bfloat16_as_ushort(l0);
                    *(uint32_t*)(g_hh + orow + c) = ph;
                    *(uint32_t*)(g_hl + orow + c) = pl;
                } else {
                    atomicAdd(out + orow + c, v0 * wgt);
                    atomicAdd(out + orow + c + 1, v1 * wgt);
                }
            }
        }
    }
}

// ------------------------- launch -------------------------
extern "C" void kernel_launch(void* const* d_in, const int* in_sizes, int n_in,
                              void* d_out, int out_size)
{
    const float* x   = (const float*)d_in[0];
    const float* gw1 = (const float*)d_in[1];
    const float* gb1 = (const float*)d_in[2];
    const float* gw2 = (const float*)d_in[3];
    const float* gb2 = (const float*)d_in[4];
    const float* ew1 = (const float*)d_in[5];
    const float* eb1 = (const float*)d_in[6];
    const float* ew2 = (const float*)d_in[7];
    const float* eb2 = (const float*)d_in[8];
    float* out = (float*)d_out;

    cudaMemsetAsync(d_out, 0, (size_t)out_size * sizeof(float));
    k_init<<<1, 32>>>();

    // precision splits (destinations are device globals selected in device code)
    k_xsplit<<<(BT * DM) / 256, 256>>>(x);
    k_wsplit<0><<<(NE * DM * HE) / 256, 256>>>(ew1);
    k_wsplit<1><<<(NE * HE * DM) / 256, 256>>>(ew2);

    // gating
    dim3 gg(GHD / 128, BT / 128);
    k_gate_gemm<<<gg, 256>>>(x, gw1, gb1);
    long long extra = (long long)out_size - (long long)BT * DM;
    float* tail = (extra >= (long long)BT * TK) ? (out + (size_t)BT * DM) : nullptr;
    k_gate2<<<BT / 8, 256>>>(gw2, gb2, tail);
    k_scan<<<1, 1>>>();
    k_scatter<<<BT / 256, 256>>>();

    // expert GEMMs (HMMA); grid covers the true per-expert bound of BT rows
    dim3 ge1(HE / 128, MAXROWS_PER_E / 128, NE);
    k_moe_mma<DM, HE, 0><<<ge1, 256>>>(eb1, nullptr);
    dim3 ge2(DM / 128, MAXROWS_PER_E / 128, NE);
    k_moe_mma<HE, DM, 1><<<ge2, 256>>>(eb2, out);
}

// round 8
// speedup vs baseline: 3.0595x; 1.5596x over previous
#include <cuda_runtime.h>
#include <cuda_bf16.h>
#include <math.h>
#include <stdint.h>

// MedicalMoE on GB300 (plain sm_103 target).
// gate fp32 -> dispatch -> bf16x3 compensated mma.sync expert GEMMs.
// Round 8: cp.async + ldmatrix pipeline (round-4 structure) + round-7 fixes
// (templated wsplit — never pass __device__ symbols from host; MAXROWS=BT).
#define BT 16384
#define DM 1024
#define HE 4096
#define NE 8
#define TK 2
#define GHD 256
#define NROWS (BT * TK)
#define MAXROWS_PER_E BT

// ------------------------- device scratch -------------------------
__device__ float g_hidden[(size_t)BT * GHD];
__device__ int   g_counts[NE];
__device__ int   g_starts[NE];
__device__ int   g_fill[NE];
__device__ int   g_eid[NROWS];
__device__ float g_ew[NROWS];
__device__ int   g_rowmap[NROWS];
__device__ float g_roww[NROWS];
__device__ __nv_bfloat16 g_xh[(size_t)BT * DM],  g_xl[(size_t)BT * DM];
__device__ __nv_bfloat16 g_w1h[(size_t)NE * DM * HE], g_w1l[(size_t)NE * DM * HE]; // [E][K][N]
__device__ __nv_bfloat16 g_w2h[(size_t)NE * HE * DM], g_w2l[(size_t)NE * HE * DM]; // [E][K][N]
__device__ __nv_bfloat16 g_hh[(size_t)NROWS * HE], g_hl[(size_t)NROWS * HE];

// ------------------------- PTX helpers -------------------------
__device__ __forceinline__ uint32_t smem_to_u32(const void* p) {
    uint32_t a;
    asm("{ .reg .u64 t; cvta.to.shared.u64 t, %1; cvt.u32.u64 %0, t; }" : "=r"(a) : "l"(p));
    return a;
}
#define CP_ASYNC16(saddr, gptr) \
    asm volatile("cp.async.cg.shared.global [%0], [%1], 16;" :: "r"(saddr), "l"(gptr) : "memory")
#define CP_COMMIT() asm volatile("cp.async.commit_group;" ::: "memory")
#define CP_WAIT(n)  asm volatile("cp.async.wait_group %0;" :: "n"(n) : "memory")
#define LDMATRIX_X4(r0,r1,r2,r3, addr) \
    asm volatile("ldmatrix.sync.aligned.m8n8.x4.shared.b16 {%0,%1,%2,%3}, [%4];" \
        : "=r"(r0),"=r"(r1),"=r"(r2),"=r"(r3) : "r"(addr) : "memory")
#define LDMATRIX_X2T(r0,r1, addr) \
    asm volatile("ldmatrix.sync.aligned.m8n8.x2.trans.shared.b16 {%0,%1}, [%2];" \
        : "=r"(r0),"=r"(r1) : "r"(addr) : "memory")
#define MMA16816(d, a, b) \
    asm volatile("mma.sync.aligned.m16n8k16.row.col.f32.bf16.bf16.f32 " \
        "{%0,%1,%2,%3}, {%4,%5,%6,%7}, {%8,%9}, {%0,%1,%2,%3};" \
        : "+f"((d)[0]),"+f"((d)[1]),"+f"((d)[2]),"+f"((d)[3]) \
        : "r"((a)[0]),"r"((a)[1]),"r"((a)[2]),"r"((a)[3]),"r"((b)[0]),"r"((b)[1]))

// ------------------------- setup kernels -------------------------
__global__ void k_init() { if (threadIdx.x < NE) g_counts[threadIdx.x] = 0; }

__global__ void k_scan() {
    int s = 0;
    for (int e = 0; e < NE; e++) { g_starts[e] = s; s += g_counts[e]; g_fill[e] = 0; }
}

__global__ void k_scatter() {
    int t = blockIdx.x * blockDim.x + threadIdx.x;
    if (t >= BT) return;
#pragma unroll
    for (int k = 0; k < TK; k++) {
        int e = g_eid[t * TK + k];
        int pos = g_starts[e] + atomicAdd(&g_fill[e], 1);
        g_rowmap[pos] = t;
        g_roww[pos] = g_ew[t * TK + k];
    }
}

__global__ __launch_bounds__(256) void k_xsplit(const float* __restrict__ x) {
    size_t i = (size_t)blockIdx.x * 256 + threadIdx.x;
    float v = x[i];
    __nv_bfloat16 h = __float2bfloat16(v);
    g_xh[i] = h;
    g_xl[i] = __float2bfloat16(v - __bfloat162float(h));
}

// hi/lo split of expert weights; destinations selected in device code only.
template <int W2>
__global__ __launch_bounds__(256) void k_wsplit(const float* __restrict__ W)
{
    size_t i = (size_t)blockIdx.x * 256 + threadIdx.x;
    float v = W[i];
    __nv_bfloat16 h = __float2bfloat16(v);
    __nv_bfloat16 l = __float2bfloat16(v - __bfloat162float(h));
    if (W2) { g_w2h[i] = h; g_w2l[i] = l; }
    else    { g_w1h[i] = h; g_w1l[i] = l; }
}

// ------------------------- gating (fp32, proven) -------------------------
__global__ __launch_bounds__(256) void k_gate_gemm(
    const float* __restrict__ X, const float* __restrict__ W, const float* __restrict__ bias)
{
    const int K = DM, N = GHD;
    __shared__ float As[8][128];
    __shared__ float Bs[8][128];
    int tid = threadIdx.x;
    int row0 = blockIdx.y * 128, col0 = blockIdx.x * 128;
    int arow = tid >> 1, acol = (tid & 1) * 4;
    int brow = tid >> 5, bcol = (tid & 31) * 4;
    int tx = tid & 15, ty = tid >> 4;
    float acc[8][8];
#pragma unroll
    for (int i = 0; i < 8; i++)
#pragma unroll
        for (int j = 0; j < 8; j++) acc[i][j] = 0.f;
    const float* Aptr = X + (size_t)(row0 + arow) * K + acol;
    const float* Bptr = W + (size_t)brow * N + col0 + bcol;
    for (int k0 = 0; k0 < K; k0 += 8) {
        float4 av = *(const float4*)(Aptr + k0);
        As[acol + 0][arow] = av.x; As[acol + 1][arow] = av.y;
        As[acol + 2][arow] = av.z; As[acol + 3][arow] = av.w;
        *(float4*)&Bs[brow][bcol] = *(const float4*)(Bptr + (size_t)k0 * N);
        __syncthreads();
#pragma unroll
        for (int kk = 0; kk < 8; kk++) {
            float a[8], b[8];
            float4 t0 = *(const float4*)&As[kk][ty * 4];
            float4 t1 = *(const float4*)&As[kk][64 + ty * 4];
            a[0]=t0.x;a[1]=t0.y;a[2]=t0.z;a[3]=t0.w;a[4]=t1.x;a[5]=t1.y;a[6]=t1.z;a[7]=t1.w;
            float4 u0 = *(const float4*)&Bs[kk][tx * 4];
            float4 u1 = *(const float4*)&Bs[kk][64 + tx * 4];
            b[0]=u0.x;b[1]=u0.y;b[2]=u0.z;b[3]=u0.w;b[4]=u1.x;b[5]=u1.y;b[6]=u1.z;b[7]=u1.w;
#pragma unroll
            for (int i = 0; i < 8; i++)
#pragma unroll
                for (int j = 0; j < 8; j++) acc[i][j] += a[i] * b[j];
        }
        __syncthreads();
    }
#pragma unroll
    for (int i = 0; i < 8; i++) {
        int r = row0 + ((i < 4) ? (ty * 4 + i) : (64 + ty * 4 + (i - 4)));
#pragma unroll
        for (int j = 0; j < 8; j++) {
            int c = col0 + ((j < 4) ? (tx * 4 + j) : (64 + tx * 4 + (j - 4)));
            float v = acc[i][j] + bias[c];
            g_hidden[(size_t)r * GHD + c] = v > 0.f ? v : 0.f;
        }
    }
}

__global__ __launch_bounds__(256) void k_gate2(
    const float* __restrict__ gw2, const float* __restrict__ gb2, float* tail)
{
    __shared__ float sW[GHD * NE];
    __shared__ float sb[NE];
    int tid = threadIdx.x;
    for (int i = tid; i < GHD * NE; i += 256) sW[i] = gw2[i];
    if (tid < NE) sb[tid] = gb2[tid];
    __syncthreads();
    int warp = tid >> 5, lane = tid & 31;
    int token = blockIdx.x * 8 + warp;
    const float* hrow = g_hidden + (size_t)token * GHD;
    float l[NE];
#pragma unroll
    for (int e = 0; e < NE; e++) l[e] = 0.f;
#pragma unroll
    for (int i = 0; i < GHD / 32; i++) {
        int r = lane + i * 32;
        float hv = hrow[r];
#pragma unroll
        for (int e = 0; e < NE; e++) l[e] += hv * sW[r * NE + e];
    }
#pragma unroll
    for (int off = 16; off > 0; off >>= 1)
#pragma unroll
        for (int e = 0; e < NE; e++) l[e] += __shfl_down_sync(0xffffffffu, l[e], off);
    if (lane == 0) {
        float p[NE]; float m = -1e30f;
#pragma unroll
        for (int e = 0; e < NE; e++) { l[e] += sb[e]; m = fmaxf(m, l[e]); }
        float s = 0.f;
#pragma unroll
        for (int e = 0; e < NE; e++) { p[e] = expf(l[e] - m); s += p[e]; }
        float inv = 1.f / s;
#pragma unroll
        for (int e = 0; e < NE; e++) p[e] *= inv;
        int b0 = 0; float v0 = p[0];
#pragma unroll
        for (int e = 1; e < NE; e++) if (p[e] > v0) { v0 = p[e]; b0 = e; }
        int b1 = -1; float v1 = -1e30f;
#pragma unroll
        for (int e = 0; e < NE; e++) if (e != b0 && p[e] > v1) { v1 = p[e]; b1 = e; }
        float d = 1.f / (v0 + v1);
        g_eid[token * TK + 0] = b0; g_ew[token * TK + 0] = v0 * d;
        g_eid[token * TK + 1] = b1; g_ew[token * TK + 1] = v1 * d;
        atomicAdd(&g_counts[b0], 1);
        atomicAdd(&g_counts[b1], 1);
        if (tail) { tail[token * TK + 0] = (float)b0; tail[token * TK + 1] = (float)b1; }
    }
}

// ------------------------- bf16x3 mma.sync grouped GEMM (cp.async + ldmatrix) -----
// CTA tile 128(M) x 128(N), K-chunk 32, double-buffered cp.async.
// A tiles: [128 m][32+8 k] bf16 (hi, lo).  B tiles: [32 k][128+8 n] bf16 (hi, lo).
#define KCH 32
#define A_STRIDE 80            // (32+8)*2 bytes per m-row
#define B_STRIDE 272           // (128+8)*2 bytes per k-row
#define A_TILE (128 * A_STRIDE)        // 10240
#define B_TILE (KCH * B_STRIDE)        // 8704
#define OFF_AH 0
#define OFF_AL A_TILE
#define OFF_BH (2 * A_TILE)
#define OFF_BL (2 * A_TILE + B_TILE)
#define BUFSZ  (2 * A_TILE + 2 * B_TILE)   // 37888
#define SMEM_MMA (2 * BUFSZ)               // 75776

// MODE 0: GEMM1 (A = gathered x hi/lo, epilogue tanh -> g_hh/g_hl)
// MODE 1: GEMM2 (A = contiguous h rows, epilogue weighted atomicAdd -> out)
template <int KDIM, int NDIM, int MODE>
__global__ __launch_bounds__(256, 1) void k_moe_mma(const float* __restrict__ bias,
                                                    float* __restrict__ out)
{
    int e = blockIdx.z;
    int rows = g_counts[e];
    int base = g_starts[e];
    int row0 = blockIdx.y * 128;
    if (row0 >= rows) return;
    int col0 = blockIdx.x * 128;

    extern __shared__ char smem[];
    uint32_t sb = smem_to_u32(smem);
    int tid = threadIdx.x, wid = tid >> 5, lane = tid & 31;

    // ---- global load mapping ----
    int am_row = tid >> 1, a_hf = tid & 1;   // A: 2 threads/row, 2 x 16B each
    int bk_row = tid >> 3, b_sg = tid & 7;   // B: 8 threads/k-row, 2 x 16B each

    const __nv_bfloat16 *APH, *APL;
    size_t aoff;
    int arc = (row0 + am_row < rows) ? (row0 + am_row) : (rows - 1);
    if (MODE == 0) {
        APH = g_xh; APL = g_xl;
        aoff = (size_t)g_rowmap[base + arc] * KDIM;
    } else {
        APH = g_hh; APL = g_hl;
        aoff = (size_t)(base + arc) * KDIM;
    }
    const __nv_bfloat16* BPH = (MODE == 0 ? g_w1h : g_w2h) + (size_t)e * KDIM * NDIM;
    const __nv_bfloat16* BPL = (MODE == 0 ? g_w1l : g_w2l) + (size_t)e * KDIM * NDIM;

    uint32_t sA = sb + am_row * A_STRIDE + a_hf * 32;
    uint32_t sB = sb + bk_row * B_STRIDE + b_sg * 32;

    auto load_chunk = [&](int buf, int kc) {
        uint32_t bb = buf * BUFSZ;
        const __nv_bfloat16* ga  = APH + aoff + kc * KCH + a_hf * 16;
        const __nv_bfloat16* gal = APL + aoff + kc * KCH + a_hf * 16;
        CP_ASYNC16(sA + bb + OFF_AH, ga);
        CP_ASYNC16(sA + bb + OFF_AH + 16, ga + 8);
        CP_ASYNC16(sA + bb + OFF_AL, gal);
        CP_ASYNC16(sA + bb + OFF_AL + 16, gal + 8);
        const __nv_bfloat16* gb  = BPH + (size_t)(kc * KCH + bk_row) * NDIM + col0 + b_sg * 16;
        const __nv_bfloat16* gbl = BPL + (size_t)(kc * KCH + bk_row) * NDIM + col0 + b_sg * 16;
        CP_ASYNC16(sB + bb + OFF_BH, gb);
        CP_ASYNC16(sB + bb + OFF_BH + 16, gb + 8);
        CP_ASYNC16(sB + bb + OFF_BL, gbl);
        CP_ASYNC16(sB + bb + OFF_BL + 16, gbl + 8);
        CP_COMMIT();
    };

    // ---- ldmatrix fragment addresses ----
    int warp_m = wid & 3, warp_n = wid >> 2;
    int a_row_l = (lane & 7) + ((lane >> 3) & 1) * 8;
    int a_k_l   = ((lane >> 4) & 1) * 8;
    uint32_t aAddr0 = sb + (warp_m * 32 + a_row_l) * A_STRIDE + a_k_l * 2;
    uint32_t bAddr0 = sb + (lane & 15) * B_STRIDE + warp_n * 128;

    float acc[2][8][4];
#pragma unroll
    for (int mf = 0; mf < 2; mf++)
#pragma unroll
        for (int nf = 0; nf < 8; nf++)
#pragma unroll
            for (int q = 0; q < 4; q++) acc[mf][nf][q] = 0.f;

    const int NK = KDIM / KCH;
    load_chunk(0, 0);
    load_chunk(1, 1);

    for (int kc = 0; kc < NK; kc++) {
        if (kc + 1 < NK) CP_WAIT(1); else CP_WAIT(0);
        __syncthreads();
        uint32_t bb = (kc & 1) * BUFSZ;
#pragma unroll
        for (int ks = 0; ks < 2; ks++) {
            uint32_t a_h[2][4], a_l[2][4];
#pragma unroll
            for (int mf = 0; mf < 2; mf++) {
                uint32_t ad = aAddr0 + bb + mf * 16 * A_STRIDE + ks * 32;
                LDMATRIX_X4(a_h[mf][0], a_h[mf][1], a_h[mf][2], a_h[mf][3], ad + OFF_AH);
                LDMATRIX_X4(a_l[mf][0], a_l[mf][1], a_l[mf][2], a_l[mf][3], ad + OFF_AL);
            }
#pragma unroll
            for (int nf = 0; nf < 8; nf++) {
                uint32_t bd = bAddr0 + bb + ks * 16 * B_STRIDE + nf * 16;
                uint32_t b_h[2], b_l[2];
                LDMATRIX_X2T(b_h[0], b_h[1], bd + OFF_BH);
                LDMATRIX_X2T(b_l[0], b_l[1], bd + OFF_BL);
#pragma unroll
                for (int mf = 0; mf < 2; mf++) {
                    MMA16816(acc[mf][nf], a_h[mf], b_h);
                    MMA16816(acc[mf][nf], a_h[mf], b_l);
                    MMA16816(acc[mf][nf], a_l[mf], b_h);
                }
            }
        }
        __syncthreads();
        if (kc + 2 < NK) load_chunk(kc & 1, kc + 2);
    }

    // ---- epilogue (register accumulators) ----
    int rb = row0 + warp_m * 32 + (lane >> 2);
    int cb = col0 + warp_n * 64 + (lane & 3) * 2;
    const float* bp = bias + (size_t)e * NDIM;
#pragma unroll
    for (int mf = 0; mf < 2; mf++) {
#pragma unroll
        for (int half2 = 0; half2 < 2; half2++) {
            int r = rb + mf * 16 + half2 * 8;
            if (r >= rows) continue;
            size_t orow; float wgt = 1.f;
            if (MODE == 0) {
                orow = (size_t)(base + r) * NDIM;
            } else {
                int pos = base + r;
                orow = (size_t)g_rowmap[pos] * NDIM;
                wgt = g_roww[pos];
            }
#pragma unroll
            for (int nf = 0; nf < 8; nf++) {
                int c = cb + nf * 8;
                float v0 = acc[mf][nf][half2 * 2 + 0] + bp[c];
                float v1 = acc[mf][nf][half2 * 2 + 1] + bp[c + 1];
                if (MODE == 0) {
                    float t0 = tanhf(v0), t1 = tanhf(v1);
                    __nv_bfloat16 h0 = __float2bfloat16(t0), h1 = __float2bfloat16(t1);
                    __nv_bfloat16 l0 = __float2bfloat16(t0 - __bfloat162float(h0));
                    __nv_bfloat16 l1 = __float2bfloat16(t1 - __bfloat162float(h1));
                    uint32_t ph = ((uint32_t)__bfloat16_as_ushort(h1) << 16) | __bfloat16_as_ushort(h0);
                    uint32_t pl = ((uint32_t)__bfloat16_as_ushort(l1) << 16) | __bfloat16_as_ushort(l0);
                    *(uint32_t*)(g_hh + orow + c) = ph;
                    *(uint32_t*)(g_hl + orow + c) = pl;
                } else {
                    atomicAdd(out + orow + c, v0 * wgt);
                    atomicAdd(out + orow + c + 1, v1 * wgt);
                }
            }
        }
    }
}

// ------------------------- launch -------------------------
extern "C" void kernel_launch(void* const* d_in, const int* in_sizes, int n_in,
                              void* d_out, int out_size)
{
    const float* x   = (const float*)d_in[0];
    const float* gw1 = (const float*)d_in[1];
    const float* gb1 = (const float*)d_in[2];
    const float* gw2 = (const float*)d_in[3];
    const float* gb2 = (const float*)d_in[4];
    const float* ew1 = (const float*)d_in[5];
    const float* eb1 = (const float*)d_in[6];
    const float* ew2 = (const float*)d_in[7];
    const float* eb2 = (const float*)d_in[8];
    float* out = (float*)d_out;

    cudaFuncSetAttribute(k_moe_mma<DM, HE, 0>, cudaFuncAttributeMaxDynamicSharedMemorySize, SMEM_MMA);
    cudaFuncSetAttribute(k_moe_mma<HE, DM, 1>, cudaFuncAttributeMaxDynamicSharedMemorySize, SMEM_MMA);

    cudaMemsetAsync(d_out, 0, (size_t)out_size * sizeof(float));
    k_init<<<1, 32>>>();

    // precision splits (destinations are device globals selected in device code)
    k_xsplit<<<(BT * DM) / 256, 256>>>(x);
    k_wsplit<0><<<(NE * DM * HE) / 256, 256>>>(ew1);
    k_wsplit<1><<<(NE * HE * DM) / 256, 256>>>(ew2);

    // gating
    dim3 gg(GHD / 128, BT / 128);
    k_gate_gemm<<<gg, 256>>>(x, gw1, gb1);
    long long extra = (long long)out_size - (long long)BT * DM;
    float* tail = (extra >= (long long)BT * TK) ? (out + (size_t)BT * DM) : nullptr;
    k_gate2<<<BT / 8, 256>>>(gw2, gb2, tail);
    k_scan<<<1, 1>>>();
    k_scatter<<<BT / 256, 256>>>();

    // expert GEMMs (HMMA, cp.async + ldmatrix, grid covers BT rows per expert)
    dim3 ge1(HE / 128, MAXROWS_PER_E / 128, NE);
    k_moe_mma<DM, HE, 0><<<ge1, 256, SMEM_MMA>>>(eb1, nullptr);
    dim3 ge2(DM / 128, MAXROWS_PER_E / 128, NE);
    k_moe_mma<HE, DM, 1><<<ge2, 256, SMEM_MMA>>>(eb2, out);
}